// round 5
// baseline (speedup 1.0000x reference)
#include <cuda_runtime.h>
#include <cuda_fp16.h>

#define DD    64
#define HID   128
#define NCLS  5
#define MAXU  100000
#define MAXM  50000
#define MAXE  1000000

// Scratch (allocation-free per harness rules). U/I stored as fp16.
__device__ unsigned short g_Uh[(size_t)MAXU * HID];   // 25.6 MB
__device__ unsigned short g_Ih[(size_t)MAXM * HID];   // 12.8 MB
__device__ int g_is64;

// ---- packed f32x2 helpers (sm_100) ----
__device__ __forceinline__ unsigned long long ffma2(unsigned long long a,
                                                    unsigned long long b,
                                                    unsigned long long c) {
    unsigned long long d;
    asm("fma.rn.f32x2 %0, %1, %2, %3;" : "=l"(d) : "l"(a), "l"(b), "l"(c));
    return d;
}
__device__ __forceinline__ float2 u2f(unsigned long long v) {
    float2 r;
    asm("mov.b64 {%0, %1}, %2;" : "=f"(r.x), "=f"(r.y) : "l"(v));
    return r;
}
__device__ __forceinline__ unsigned long long pack2(float x, float y) {
    unsigned long long r;
    asm("mov.b64 %0, {%1, %2};" : "=l"(r) : "f"(x), "f"(y));
    return r;
}

// ---------------------------------------------------------------------------
// Probe int64-vs-int32 index dtype (deterministic; reads only safe range).
// ---------------------------------------------------------------------------
__global__ void probe_kernel(const unsigned long long* __restrict__ p, int n) {
    __shared__ int bad;
    if (threadIdx.x == 0) bad = 0;
    __syncthreads();
    int m = n / 2;
    int lim = n < 2048 ? n : 2048;
    if (lim > m) lim = m;
    int b = 0;
    for (int i = threadIdx.x; i < lim; i += blockDim.x)
        if (p[i] >= 200000ULL) b = 1;
    if (b) atomicOr(&bad, 1);
    __syncthreads();
    if (threadIdx.x == 0) g_is64 = bad ? 0 : 1;
}

__device__ __forceinline__ int ldidx(const void* p, long i, int is64) {
    return is64 ? (int)__ldg((const long long*)p + i) : __ldg((const int*)p + i);
}

// ---------------------------------------------------------------------------
// Pre v3: register-tiled GEMM, W stored DUPLICATED in smem so the inner loop
// has zero packing MOVs. Block = 256 threads (16tr x 16tc), thread tile
// 8 rows x 8 cols; k=64 in 2 halves of 32.
//   Fs[32][128]  16KB  features transposed [k][row]
//   Wd[32][256]  32KB  weights transposed+duplicated [k][2c]=[k][2c+1]=w[c][k]
// XOR swizzles on both (fill is a transpose scatter -> would be 8-way bank
// conflicted without them; compute loads keep alignment because swizzle
// granularity >= load width).
// ---------------------------------------------------------------------------
#define FIDX(k, r)  ((k) * 128 + ((r) ^ (((k) & 3) << 3)))
#define WIDX(k, c2) ((k) * 256 + ((c2) ^ (((k) & 7) << 2)))

__global__ void __launch_bounds__(256, 2)
pre3_kernel(const float* __restrict__ ufeat, const float* __restrict__ ifeat,
            const float* __restrict__ W1, const float* __restrict__ b1,
            int nu, int nm, int blocksU) {
    __shared__ __align__(16) float Fs[32 * 128];   // 16KB
    __shared__ __align__(16) float Wd[32 * 256];   // 32KB (total = 48KB exactly)

    bool isU = (int)blockIdx.x < blocksU;
    int rowbase = (isU ? blockIdx.x : blockIdx.x - blocksU) * 128;
    int nrows = isU ? nu : nm;
    const float4* F4 = (const float4*)(isU ? ufeat : ifeat);   // row = 16 float4
    const float4* W14 = (const float4*)W1;                     // row = 32 float4
    int woff = isU ? 0 : 16;
    unsigned short* outb = isU ? g_Uh : g_Ih;

    int tid = threadIdx.x;
    int tr = tid >> 4, tc = tid & 15;
    int r0 = tr * 8, c0 = tc * 8;

    unsigned long long acc[4][8];
#pragma unroll
    for (int a = 0; a < 4; a++)
#pragma unroll
        for (int j = 0; j < 8; j++) acc[a][j] = 0ULL;

#pragma unroll
    for (int h = 0; h < 2; h++) {
        if (h) __syncthreads();
#pragma unroll
        for (int it = 0; it < 4; it++) {
            int idx = it * 256 + tid;        // 0..1023
            int r = idx >> 3;                // 0..127 (F row / W col)
            int f = idx & 7;                 // float4 within k-half
            int kq = f * 4;
            int rr = rowbase + r;
            if (rr >= nrows) rr = nrows - 1;
            float4 v = F4[(size_t)rr * 16 + h * 8 + f];
            Fs[FIDX(kq + 0, r)] = v.x;
            Fs[FIDX(kq + 1, r)] = v.y;
            Fs[FIDX(kq + 2, r)] = v.z;
            Fs[FIDX(kq + 3, r)] = v.w;
            float4 u = W14[(size_t)r * 32 + woff + h * 8 + f];
            int b0 = WIDX(kq + 0, 2 * r);
            int b1i = WIDX(kq + 1, 2 * r);
            int b2 = WIDX(kq + 2, 2 * r);
            int b3 = WIDX(kq + 3, 2 * r);
            Wd[b0] = u.x; Wd[b0 + 1] = u.x;
            Wd[b1i] = u.y; Wd[b1i + 1] = u.y;
            Wd[b2] = u.z; Wd[b2 + 1] = u.z;
            Wd[b3] = u.w; Wd[b3 + 1] = u.w;
        }
        __syncthreads();

#pragma unroll 4
        for (int k = 0; k < 32; k++) {
            unsigned long long f2[4];
#pragma unroll
            for (int rp = 0; rp < 4; rp++)
                f2[rp] = *(const unsigned long long*)&Fs[FIDX(k, r0 + 2 * rp)];
            ulonglong2 wd2[4];
#pragma unroll
            for (int m = 0; m < 4; m++)
                wd2[m] = *(const ulonglong2*)&Wd[WIDX(k, 2 * c0 + 4 * m)];
#pragma unroll
            for (int rp = 0; rp < 4; rp++) {
#pragma unroll
                for (int m = 0; m < 4; m++) {
                    acc[rp][2 * m]     = ffma2(f2[rp], wd2[m].x, acc[rp][2 * m]);
                    acc[rp][2 * m + 1] = ffma2(f2[rp], wd2[m].y, acc[rp][2 * m + 1]);
                }
            }
        }
    }

    float bv[8];
#pragma unroll
    for (int j = 0; j < 8; j++) bv[j] = 0.f;
    if (!isU) {
        float4 ba = *(const float4*)(b1 + c0);
        float4 bbv = *(const float4*)(b1 + c0 + 4);
        bv[0] = ba.x; bv[1] = ba.y; bv[2] = ba.z; bv[3] = ba.w;
        bv[4] = bbv.x; bv[5] = bbv.y; bv[6] = bbv.z; bv[7] = bbv.w;
    }

#pragma unroll
    for (int rp = 0; rp < 4; rp++) {
        float x[8], y[8];
#pragma unroll
        for (int j = 0; j < 8; j++) {
            float2 t = u2f(acc[rp][j]);
            x[j] = t.x + bv[j];
            y[j] = t.y + bv[j];
        }
        int rowA = rowbase + r0 + rp * 2;
        int rowB = rowA + 1;
        if (rowA < nrows) {
            __half2 h0 = __floats2half2_rn(x[0], x[1]);
            __half2 h1 = __floats2half2_rn(x[2], x[3]);
            __half2 h2 = __floats2half2_rn(x[4], x[5]);
            __half2 h3 = __floats2half2_rn(x[6], x[7]);
            *(uint4*)(outb + (size_t)rowA * HID + c0) =
                make_uint4(*(unsigned*)&h0, *(unsigned*)&h1,
                           *(unsigned*)&h2, *(unsigned*)&h3);
        }
        if (rowB < nrows) {
            __half2 h0 = __floats2half2_rn(y[0], y[1]);
            __half2 h1 = __floats2half2_rn(y[2], y[3]);
            __half2 h2 = __floats2half2_rn(y[4], y[5]);
            __half2 h3 = __floats2half2_rn(y[6], y[7]);
            *(uint4*)(outb + (size_t)rowB * HID + c0) =
                make_uint4(*(unsigned*)&h0, *(unsigned*)&h1,
                           *(unsigned*)&h2, *(unsigned*)&h3);
        }
    }
}

// ---------------------------------------------------------------------------
// Edge v3: 8 lanes per edge, ILP x2 (each group handles edges e and e+4 per
// iteration -> 8 LDG.128 in flight, two independent GEMV+butterfly chains).
// Indices read directly from the input buffers (uniform is64 branch).
// ---------------------------------------------------------------------------
__device__ __forceinline__ float edge_compute(uint4 u0, uint4 u1, uint4 v0, uint4 v1,
                                              const unsigned long long (*w2)[8],
                                              __half2 z2, int hl) {
    unsigned long long h2[8];
    {
        const __half2* ua = (const __half2*)&u0;
        const __half2* va = (const __half2*)&v0;
        const __half2* ub = (const __half2*)&u1;
        const __half2* vb = (const __half2*)&v1;
#pragma unroll
        for (int j = 0; j < 4; j++) {
            __half2 hv = __hmax2(__hadd2(ua[j], va[j]), z2);
            float2 f = __half22float2(hv);
            h2[j] = pack2(f.x, f.y);
        }
#pragma unroll
        for (int j = 0; j < 4; j++) {
            __half2 hv = __hmax2(__hadd2(ub[j], vb[j]), z2);
            float2 f = __half22float2(hv);
            h2[4 + j] = pack2(f.x, f.y);
        }
    }
    float acc[NCLS];
#pragma unroll
    for (int c = 0; c < NCLS; c++) {
        unsigned long long a2 = 0ULL;
#pragma unroll
        for (int j = 0; j < 8; j++)
            a2 = ffma2(h2[j], w2[c][j], a2);
        float2 t = u2f(a2);
        acc[c] = t.x + t.y;
    }
#pragma unroll
    for (int off = 4; off; off >>= 1) {
#pragma unroll
        for (int c = 0; c < NCLS; c++)
            acc[c] += __shfl_xor_sync(0xffffffffu, acc[c], off);
    }
    return (hl == 0) ? acc[0]
         : (hl == 1) ? acc[1]
         : (hl == 2) ? acc[2]
         : (hl == 3) ? acc[3]
                     : acc[4];
}

__global__ void __launch_bounds__(128, 3)
edge3_kernel(const float* __restrict__ W2, const float* __restrict__ b2,
             const void* __restrict__ srcraw, const void* __restrict__ dstraw,
             float* __restrict__ out, long E) {
    int lane = threadIdx.x & 31;
    int g = lane >> 3;
    int hl = lane & 7;
    int is64 = g_is64;

    unsigned long long w2[NCLS][8];
#pragma unroll
    for (int c = 0; c < NCLS; c++) {
        const float4* p = (const float4*)(W2 + c * HID + hl * 16);
        float4 a = p[0], b = p[1], cc = p[2], d = p[3];
        w2[c][0] = pack2(a.x, a.y);   w2[c][1] = pack2(a.z, a.w);
        w2[c][2] = pack2(b.x, b.y);   w2[c][3] = pack2(b.z, b.w);
        w2[c][4] = pack2(cc.x, cc.y); w2[c][5] = pack2(cc.z, cc.w);
        w2[c][6] = pack2(d.x, d.y);   w2[c][7] = pack2(d.z, d.w);
    }
    float bb = (hl < NCLS) ? b2[hl] : 0.f;
    __half2 z2 = __float2half2_rn(0.f);

    long warpId = (long)blockIdx.x * (blockDim.x >> 5) + (threadIdx.x >> 5);
    long stride = (long)gridDim.x * (blockDim.x >> 5) * 8;

    for (long e0 = warpId * 8 + g; e0 < E; e0 += stride) {
        long e1 = e0 + 4;
        bool m1 = e1 < E;
        long ee1 = m1 ? e1 : e0;

        int s0 = ldidx(srcraw, e0, is64);
        int d0 = ldidx(dstraw, e0, is64);
        int s1 = ldidx(srcraw, ee1, is64);
        int d1 = ldidx(dstraw, ee1, is64);

        const uint4* Up0 = (const uint4*)g_Uh + (size_t)s0 * 16 + hl * 2;
        const uint4* Ip0 = (const uint4*)g_Ih + (size_t)d0 * 16 + hl * 2;
        const uint4* Up1 = (const uint4*)g_Uh + (size_t)s1 * 16 + hl * 2;
        const uint4* Ip1 = (const uint4*)g_Ih + (size_t)d1 * 16 + hl * 2;
        uint4 a0 = Up0[0], a1 = Up0[1];
        uint4 b0 = Ip0[0], b1v = Ip0[1];
        uint4 c0 = Up1[0], c1 = Up1[1];
        uint4 d0v = Ip1[0], d1v = Ip1[1];

        float r0 = edge_compute(a0, a1, b0, b1v, w2, z2, hl);
        float r1 = edge_compute(c0, c1, d0v, d1v, w2, z2, hl);

        if (hl < NCLS) {
            out[e0 * NCLS + hl] = r0 + bb;
            if (m1) out[e1 * NCLS + hl] = r1 + bb;
        }
    }
}

// ---------------------------------------------------------------------------
// Inputs (metadata order): ufeat, ifeat, W1, b1, W2, b2, src_idx, dst_idx
// ---------------------------------------------------------------------------
extern "C" void kernel_launch(void* const* d_in, const int* in_sizes, int n_in,
                              void* d_out, int out_size) {
    const float* ufeat = (const float*)d_in[0];
    const float* ifeat = (const float*)d_in[1];
    const float* W1    = (const float*)d_in[2];
    const float* b1    = (const float*)d_in[3];
    const float* W2    = (const float*)d_in[4];
    const float* b2    = (const float*)d_in[5];
    const void*  src   = d_in[6];
    const void*  dst   = d_in[7];

    int nu = in_sizes[0] / DD;
    int nm = in_sizes[1] / DD;
    int E  = in_sizes[6];

    probe_kernel<<<1, 256>>>((const unsigned long long*)src, E);

    int blocksU = (nu + 127) / 128;
    int blocksI = (nm + 127) / 128;
    pre3_kernel<<<blocksU + blocksI, 256>>>(ufeat, ifeat, W1, b1, nu, nm, blocksU);

    edge3_kernel<<<444, 128>>>(W2, b2, src, dst, (float*)d_out, (long)E);
}

// round 6
// speedup vs baseline: 1.6597x; 1.6597x over previous
#include <cuda_runtime.h>
#include <cuda_fp16.h>

#define DD    64
#define HID   128
#define NCLS  5
#define MAXU  100000
#define MAXM  50000

// Scratch (allocation-free per harness rules). U/I stored as fp16.
__device__ unsigned short g_Uh[(size_t)MAXU * HID];   // 25.6 MB
__device__ unsigned short g_Ih[(size_t)MAXM * HID];   // 12.8 MB
__device__ int g_is64;

// ---- packed f32x2 helpers (sm_100) ----
__device__ __forceinline__ unsigned long long ffma2(unsigned long long a,
                                                    unsigned long long b,
                                                    unsigned long long c) {
    unsigned long long d;
    asm("fma.rn.f32x2 %0, %1, %2, %3;" : "=l"(d) : "l"(a), "l"(b), "l"(c));
    return d;
}
__device__ __forceinline__ float2 u2f(unsigned long long v) {
    float2 r;
    asm("mov.b64 {%0, %1}, %2;" : "=f"(r.x), "=f"(r.y) : "l"(v));
    return r;
}
__device__ __forceinline__ unsigned long long pack2(float x, float y) {
    unsigned long long r;
    asm("mov.b64 %0, {%1, %2};" : "=l"(r) : "f"(x), "f"(y));
    return r;
}

// ---------------------------------------------------------------------------
// Probe int64-vs-int32 index dtype (deterministic; reads only safe range).
// ---------------------------------------------------------------------------
__global__ void probe_kernel(const unsigned long long* __restrict__ p, int n) {
    __shared__ int bad;
    if (threadIdx.x == 0) bad = 0;
    __syncthreads();
    int m = n / 2;
    int lim = n < 256 ? n : 256;
    if (lim > m) lim = m;
    int b = 0;
    for (int i = threadIdx.x; i < lim; i += blockDim.x)
        if (p[i] >= 200000ULL) b = 1;
    if (b) atomicOr(&bad, 1);
    __syncthreads();
    if (threadIdx.x == 0) g_is64 = bad ? 0 : 1;
}

__device__ __forceinline__ int ldidx(const void* p, long i, int is64) {
    return is64 ? (int)__ldg((const long long*)p + i) : __ldg((const int*)p + i);
}

// ---------------------------------------------------------------------------
// Pre v2 (R4-proven): register-tiled GEMM. Block = 256 threads (16tr x 16tc),
// thread tile 8 rows x 8 cols, k=64 in 2 halves of 32 (two 16KB transposed
// smem tiles). FFMA2 packed over ROW PAIRS -> no horizontal reduction.
// ---------------------------------------------------------------------------
__global__ void __launch_bounds__(256, 2)
pre2_kernel(const float* __restrict__ ufeat, const float* __restrict__ ifeat,
            const float* __restrict__ W1, const float* __restrict__ b1,
            int nu, int nm, int blocksU) {
    __shared__ __align__(16) float Fs[32 * 128];   // 16KB [k][row]
    __shared__ __align__(16) float Wt[32 * 128];   // 16KB [k][col]

    bool isU = (int)blockIdx.x < blocksU;
    int rowbase = (isU ? blockIdx.x : blockIdx.x - blocksU) * 128;
    int nrows = isU ? nu : nm;
    const float4* F4 = (const float4*)(isU ? ufeat : ifeat);   // row = 16 float4
    const float4* W14 = (const float4*)W1;                     // row = 32 float4
    int woff = isU ? 0 : 16;
    unsigned short* outb = isU ? g_Uh : g_Ih;

    int tid = threadIdx.x;
    int tr = tid >> 4, tc = tid & 15;
    int r0 = tr * 8, c0 = tc * 8;

    unsigned long long acc[4][8];
#pragma unroll
    for (int a = 0; a < 4; a++)
#pragma unroll
        for (int j = 0; j < 8; j++) acc[a][j] = 0ULL;

#pragma unroll
    for (int h = 0; h < 2; h++) {
        if (h) __syncthreads();
#pragma unroll
        for (int it = 0; it < 4; it++) {
            int idx = it * 256 + tid;        // 0..1023
            int r = idx >> 3;                // 0..127 (row or col)
            int f = idx & 7;                 // float4 within k-half
            int rr = rowbase + r;
            if (rr >= nrows) rr = nrows - 1;
            float4 v = F4[(size_t)rr * 16 + h * 8 + f];
            Fs[(f * 4 + 0) * 128 + r] = v.x;
            Fs[(f * 4 + 1) * 128 + r] = v.y;
            Fs[(f * 4 + 2) * 128 + r] = v.z;
            Fs[(f * 4 + 3) * 128 + r] = v.w;
            float4 u = W14[(size_t)r * 32 + woff + h * 8 + f];
            Wt[(f * 4 + 0) * 128 + r] = u.x;
            Wt[(f * 4 + 1) * 128 + r] = u.y;
            Wt[(f * 4 + 2) * 128 + r] = u.z;
            Wt[(f * 4 + 3) * 128 + r] = u.w;
        }
        __syncthreads();

#pragma unroll 4
        for (int k = 0; k < 32; k++) {
            const unsigned long long* frow =
                (const unsigned long long*)&Fs[k * 128 + r0];
            unsigned long long f2[4];
            f2[0] = frow[0]; f2[1] = frow[1]; f2[2] = frow[2]; f2[3] = frow[3];
            float4 wa = *(const float4*)&Wt[k * 128 + c0];
            float4 wb = *(const float4*)&Wt[k * 128 + c0 + 4];
            unsigned long long wd[8];
            wd[0] = pack2(wa.x, wa.x); wd[1] = pack2(wa.y, wa.y);
            wd[2] = pack2(wa.z, wa.z); wd[3] = pack2(wa.w, wa.w);
            wd[4] = pack2(wb.x, wb.x); wd[5] = pack2(wb.y, wb.y);
            wd[6] = pack2(wb.z, wb.z); wd[7] = pack2(wb.w, wb.w);
#pragma unroll
            for (int rp = 0; rp < 4; rp++)
#pragma unroll
                for (int j = 0; j < 8; j++)
                    acc[rp][j] = ffma2(f2[rp], wd[j], acc[rp][j]);
        }
    }

    float bv[8];
#pragma unroll
    for (int j = 0; j < 8; j++) bv[j] = 0.f;
    if (!isU) {
#pragma unroll
        for (int j = 0; j < 8; j++) bv[j] = b1[c0 + j];
    }

#pragma unroll
    for (int rp = 0; rp < 4; rp++) {
        float x[8], y[8];
#pragma unroll
        for (int j = 0; j < 8; j++) {
            float2 t = u2f(acc[rp][j]);
            x[j] = t.x + bv[j];
            y[j] = t.y + bv[j];
        }
        int rowA = rowbase + r0 + rp * 2;
        int rowB = rowA + 1;
        if (rowA < nrows) {
            __half2 h0 = __floats2half2_rn(x[0], x[1]);
            __half2 h1 = __floats2half2_rn(x[2], x[3]);
            __half2 h2 = __floats2half2_rn(x[4], x[5]);
            __half2 h3 = __floats2half2_rn(x[6], x[7]);
            *(uint4*)(outb + (size_t)rowA * HID + c0) =
                make_uint4(*(unsigned*)&h0, *(unsigned*)&h1,
                           *(unsigned*)&h2, *(unsigned*)&h3);
        }
        if (rowB < nrows) {
            __half2 h0 = __floats2half2_rn(y[0], y[1]);
            __half2 h1 = __floats2half2_rn(y[2], y[3]);
            __half2 h2 = __floats2half2_rn(y[4], y[5]);
            __half2 h3 = __floats2half2_rn(y[6], y[7]);
            *(uint4*)(outb + (size_t)rowB * HID + c0) =
                make_uint4(*(unsigned*)&h0, *(unsigned*)&h1,
                           *(unsigned*)&h2, *(unsigned*)&h3);
        }
    }
}

// ---------------------------------------------------------------------------
// Edge v2 (R4-proven shape): 8 lanes per edge (4 edges/warp), packed-FFMA2
// GEMV with W2 in registers, 3-step butterfly, idx prefetch one iteration
// ahead. Changes vs R4: raw-index reads (no convert kernel), grid 592 so
// occupancy is 4 blocks/SM instead of 3 (was grid-limited at 444).
// ---------------------------------------------------------------------------
__global__ void __launch_bounds__(128) edge2_kernel(
        const float* __restrict__ W2, const float* __restrict__ b2,
        const void* __restrict__ srcraw, const void* __restrict__ dstraw,
        float* __restrict__ out, long E) {
    int lane = threadIdx.x & 31;
    int g = lane >> 3;
    int hl = lane & 7;
    int is64 = g_is64;

    unsigned long long w2[NCLS][8];
#pragma unroll
    for (int c = 0; c < NCLS; c++) {
        const float4* p = (const float4*)(W2 + c * HID + hl * 16);
        float4 a = p[0], b = p[1], cc = p[2], d = p[3];
        w2[c][0] = pack2(a.x, a.y);   w2[c][1] = pack2(a.z, a.w);
        w2[c][2] = pack2(b.x, b.y);   w2[c][3] = pack2(b.z, b.w);
        w2[c][4] = pack2(cc.x, cc.y); w2[c][5] = pack2(cc.z, cc.w);
        w2[c][6] = pack2(d.x, d.y);   w2[c][7] = pack2(d.z, d.w);
    }
    float bb = (hl < NCLS) ? b2[hl] : 0.f;
    __half2 z2 = __float2half2_rn(0.f);

    long warpId = (long)blockIdx.x * (blockDim.x >> 5) + (threadIdx.x >> 5);
    long stride4 = (long)gridDim.x * (blockDim.x >> 5) * 4;
    long e = warpId * 4 + g;
    if (e >= E) return;                          // warp-uniform (E % 4 == 0)

    int s = ldidx(srcraw, e, is64);
    int dI = ldidx(dstraw, e, is64);
    while (true) {
        long en = e + stride4;
        int sn = 0, dn = 0;
        bool more = (en < E);                    // warp-uniform
        if (more) { sn = ldidx(srcraw, en, is64); dn = ldidx(dstraw, en, is64); }

        const uint4* Up = (const uint4*)g_Uh + (size_t)s * 16 + hl * 2;
        const uint4* Ip = (const uint4*)g_Ih + (size_t)dI * 16 + hl * 2;
        uint4 u0 = Up[0], u1 = Up[1];
        uint4 v0 = Ip[0], v1 = Ip[1];

        unsigned long long h2[8];
        {
            const __half2* ua = (const __half2*)&u0;
            const __half2* va = (const __half2*)&v0;
            const __half2* ub = (const __half2*)&u1;
            const __half2* vb = (const __half2*)&v1;
#pragma unroll
            for (int j = 0; j < 4; j++) {
                __half2 hv = __hmax2(__hadd2(ua[j], va[j]), z2);
                float2 f = __half22float2(hv);
                h2[j] = pack2(f.x, f.y);
            }
#pragma unroll
            for (int j = 0; j < 4; j++) {
                __half2 hv = __hmax2(__hadd2(ub[j], vb[j]), z2);
                float2 f = __half22float2(hv);
                h2[4 + j] = pack2(f.x, f.y);
            }
        }

        float acc[NCLS];
#pragma unroll
        for (int c = 0; c < NCLS; c++) {
            unsigned long long a2 = 0ULL;
#pragma unroll
            for (int j = 0; j < 8; j++)
                a2 = ffma2(h2[j], w2[c][j], a2);
            float2 t = u2f(a2);
            acc[c] = t.x + t.y;
        }

#pragma unroll
        for (int off = 4; off; off >>= 1) {
#pragma unroll
            for (int c = 0; c < NCLS; c++)
                acc[c] += __shfl_xor_sync(0xffffffffu, acc[c], off);
        }

        if (hl < NCLS) {
            float r = (hl == 0) ? acc[0]
                    : (hl == 1) ? acc[1]
                    : (hl == 2) ? acc[2]
                    : (hl == 3) ? acc[3]
                                : acc[4];
            out[e * NCLS + hl] = r + bb;
        }

        if (!more) break;
        e = en; s = sn; dI = dn;
    }
}

// ---------------------------------------------------------------------------
// Inputs (metadata order): ufeat, ifeat, W1, b1, W2, b2, src_idx, dst_idx
// ---------------------------------------------------------------------------
extern "C" void kernel_launch(void* const* d_in, const int* in_sizes, int n_in,
                              void* d_out, int out_size) {
    const float* ufeat = (const float*)d_in[0];
    const float* ifeat = (const float*)d_in[1];
    const float* W1    = (const float*)d_in[2];
    const float* b1    = (const float*)d_in[3];
    const float* W2    = (const float*)d_in[4];
    const float* b2    = (const float*)d_in[5];
    const void*  src   = d_in[6];
    const void*  dst   = d_in[7];

    int nu = in_sizes[0] / DD;
    int nm = in_sizes[1] / DD;
    int E  = in_sizes[6];

    probe_kernel<<<1, 128>>>((const unsigned long long*)src, E);

    int blocksU = (nu + 127) / 128;
    int blocksI = (nm + 127) / 128;
    pre2_kernel<<<blocksU + blocksI, 256>>>(ufeat, ifeat, W1, b1, nu, nm, blocksU);

    edge2_kernel<<<592, 128>>>(W2, b2, src, dst, (float*)d_out, (long)E);
}

// round 8
// speedup vs baseline: 2.0119x; 1.2122x over previous
#include <cuda_runtime.h>
#include <cuda_fp16.h>
#include <cstdint>

#define DD    64
#define HID   128
#define NCLS  5
#define MAXU  100000
#define MAXM  50000

// Scratch (allocation-free per harness rules). U/I stored as fp16.
__device__ unsigned short g_Uh[(size_t)MAXU * HID];   // 25.6 MB
__device__ unsigned short g_Ih[(size_t)MAXM * HID];   // 12.8 MB

// ---- packed f32x2 helpers (sm_100) ----
__device__ __forceinline__ unsigned long long ffma2(unsigned long long a,
                                                    unsigned long long b,
                                                    unsigned long long c) {
    unsigned long long d;
    asm("fma.rn.f32x2 %0, %1, %2, %3;" : "=l"(d) : "l"(a), "l"(b), "l"(c));
    return d;
}
__device__ __forceinline__ float2 u2f(unsigned long long v) {
    float2 r;
    asm("mov.b64 {%0, %1}, %2;" : "=f"(r.x), "=f"(r.y) : "l"(v));
    return r;
}
__device__ __forceinline__ unsigned long long pack2(float x, float y) {
    unsigned long long r;
    asm("mov.b64 %0, {%1, %2};" : "=l"(r) : "f"(x), "f"(y));
    return r;
}

// ---------------------------------------------------------------------------
// Pre v2 (R4/R6-proven): register-tiled GEMM. Block = 256 threads
// (16tr x 16tc), thread tile 8 rows x 8 cols, k=64 in 2 halves of 32
// (two 16KB transposed smem tiles). FFMA2 packed over ROW PAIRS.
// ---------------------------------------------------------------------------
__global__ void __launch_bounds__(256, 2)
pre2_kernel(const float* __restrict__ ufeat, const float* __restrict__ ifeat,
            const float* __restrict__ W1, const float* __restrict__ b1,
            int nu, int nm, int blocksU) {
    __shared__ __align__(16) float Fs[32 * 128];   // 16KB [k][row]
    __shared__ __align__(16) float Wt[32 * 128];   // 16KB [k][col]

    bool isU = (int)blockIdx.x < blocksU;
    int rowbase = (isU ? blockIdx.x : blockIdx.x - blocksU) * 128;
    int nrows = isU ? nu : nm;
    const float4* F4 = (const float4*)(isU ? ufeat : ifeat);   // row = 16 float4
    const float4* W14 = (const float4*)W1;                     // row = 32 float4
    int woff = isU ? 0 : 16;
    unsigned short* outb = isU ? g_Uh : g_Ih;

    int tid = threadIdx.x;
    int tr = tid >> 4, tc = tid & 15;
    int r0 = tr * 8, c0 = tc * 8;

    unsigned long long acc[4][8];
#pragma unroll
    for (int a = 0; a < 4; a++)
#pragma unroll
        for (int j = 0; j < 8; j++) acc[a][j] = 0ULL;

#pragma unroll
    for (int h = 0; h < 2; h++) {
        if (h) __syncthreads();
#pragma unroll
        for (int it = 0; it < 4; it++) {
            int idx = it * 256 + tid;        // 0..1023
            int r = idx >> 3;                // 0..127 (row or col)
            int f = idx & 7;                 // float4 within k-half
            int rr = rowbase + r;
            if (rr >= nrows) rr = nrows - 1;
            float4 v = F4[(size_t)rr * 16 + h * 8 + f];
            Fs[(f * 4 + 0) * 128 + r] = v.x;
            Fs[(f * 4 + 1) * 128 + r] = v.y;
            Fs[(f * 4 + 2) * 128 + r] = v.z;
            Fs[(f * 4 + 3) * 128 + r] = v.w;
            float4 u = W14[(size_t)r * 32 + woff + h * 8 + f];
            Wt[(f * 4 + 0) * 128 + r] = u.x;
            Wt[(f * 4 + 1) * 128 + r] = u.y;
            Wt[(f * 4 + 2) * 128 + r] = u.z;
            Wt[(f * 4 + 3) * 128 + r] = u.w;
        }
        __syncthreads();

#pragma unroll 4
        for (int k = 0; k < 32; k++) {
            const unsigned long long* frow =
                (const unsigned long long*)&Fs[k * 128 + r0];
            unsigned long long f2[4];
            f2[0] = frow[0]; f2[1] = frow[1]; f2[2] = frow[2]; f2[3] = frow[3];
            float4 wa = *(const float4*)&Wt[k * 128 + c0];
            float4 wb = *(const float4*)&Wt[k * 128 + c0 + 4];
            unsigned long long wd[8];
            wd[0] = pack2(wa.x, wa.x); wd[1] = pack2(wa.y, wa.y);
            wd[2] = pack2(wa.z, wa.z); wd[3] = pack2(wa.w, wa.w);
            wd[4] = pack2(wb.x, wb.x); wd[5] = pack2(wb.y, wb.y);
            wd[6] = pack2(wb.z, wb.z); wd[7] = pack2(wb.w, wb.w);
#pragma unroll
            for (int rp = 0; rp < 4; rp++)
#pragma unroll
                for (int j = 0; j < 8; j++)
                    acc[rp][j] = ffma2(f2[rp], wd[j], acc[rp][j]);
        }
    }

    float bv[8];
#pragma unroll
    for (int j = 0; j < 8; j++) bv[j] = 0.f;
    if (!isU) {
#pragma unroll
        for (int j = 0; j < 8; j++) bv[j] = b1[c0 + j];
    }

#pragma unroll
    for (int rp = 0; rp < 4; rp++) {
        float x[8], y[8];
#pragma unroll
        for (int j = 0; j < 8; j++) {
            float2 t = u2f(acc[rp][j]);
            x[j] = t.x + bv[j];
            y[j] = t.y + bv[j];
        }
        int rowA = rowbase + r0 + rp * 2;
        int rowB = rowA + 1;
        if (rowA < nrows) {
            __half2 h0 = __floats2half2_rn(x[0], x[1]);
            __half2 h1 = __floats2half2_rn(x[2], x[3]);
            __half2 h2 = __floats2half2_rn(x[4], x[5]);
            __half2 h3 = __floats2half2_rn(x[6], x[7]);
            *(uint4*)(outb + (size_t)rowA * HID + c0) =
                make_uint4(*(unsigned*)&h0, *(unsigned*)&h1,
                           *(unsigned*)&h2, *(unsigned*)&h3);
        }
        if (rowB < nrows) {
            __half2 h0 = __floats2half2_rn(y[0], y[1]);
            __half2 h1 = __floats2half2_rn(y[2], y[3]);
            __half2 h2 = __floats2half2_rn(y[4], y[5]);
            __half2 h3 = __floats2half2_rn(y[6], y[7]);
            *(uint4*)(outb + (size_t)rowB * HID + c0) =
                make_uint4(*(unsigned*)&h0, *(unsigned*)&h1,
                           *(unsigned*)&h2, *(unsigned*)&h3);
        }
    }
}

// ---------------------------------------------------------------------------
// Edge MMA kernel. Warps are fully independent: each processes 16-edge
// chunks. Per chunk: 8-lane groups gather+relu-add h rows into a private
// 4KB smem tile (fp16, XOR-swizzled), then ldmatrix.x4 + 8x mma.m16n8k16
// against W2 fragments (fp16, built once per warp, N padded 5->8), fp32
// accumulate, predicated stores. No __syncthreads; 2 __syncwarp per chunk.
// Index dtype (int64 vs int32) probed per-block from the first 32 values.
// ---------------------------------------------------------------------------
__device__ __forceinline__ unsigned su32(const void* p) {
    return (unsigned)__cvta_generic_to_shared(p);
}

__global__ void __launch_bounds__(256, 3)
edge_mma_kernel(const float* __restrict__ W2, const float* __restrict__ b2,
                const void* __restrict__ srcraw, const void* __restrict__ dstraw,
                float* __restrict__ out, long E) {
    __shared__ __align__(128) unsigned char hs[8 * 16 * 256];  // 32KB, 4KB/warp

    int tid = threadIdx.x;
    int w = tid >> 5, lane = tid & 31;
    unsigned char* hp = hs + w * 4096;

    // ---- inline is64 probe (identical result in every warp) ----
    long n64avail = E / 2;                       // u64s readable either way
    int pid = (lane < n64avail) ? lane : 0;
    unsigned long long pv = ((const unsigned long long*)srcraw)[pid];
    unsigned bigmask = __ballot_sync(0xffffffffu, pv >= 200000ULL);
    int is64 = (bigmask == 0u);

    // ---- B fragments: W2 as fp16 in mma.m16n8k16 col layout, built once ----
    // lane holds n = lane>>2 (cols 0..7; >=NCLS zero), k = (lane&3)*2 {+1},
    // second reg at k+8; one fragment pair per 16-wide k-tile.
    int nB = lane >> 2;
    int kb = (lane & 3) * 2;
    unsigned bfrag[8][2];
#pragma unroll
    for (int kt = 0; kt < 8; kt++) {
#pragma unroll
        for (int j = 0; j < 2; j++) {
            int k0 = kt * 16 + kb + j * 8;
            float f0 = (nB < NCLS) ? __ldg(W2 + nB * HID + k0) : 0.f;
            float f1 = (nB < NCLS) ? __ldg(W2 + nB * HID + k0 + 1) : 0.f;
            __half2 hh = __floats2half2_rn(f0, f1);
            bfrag[kt][j] = *(unsigned*)&hh;
        }
    }
    // bias for this lane's two output columns
    int cA = (lane & 3) * 2, cB = cA + 1;
    float bA = (cA < NCLS) ? __ldg(b2 + cA) : 0.f;
    float bB = (cB < NCLS) ? __ldg(b2 + cB) : 0.f;

    int g = lane >> 3, hl = lane & 7;
    __half2 z2 = __float2half2_rn(0.f);

    long chunk0 = ((long)blockIdx.x * 8 + w) * 16;
    long stride = (long)gridDim.x * 8 * 16;

    for (long e0 = chunk0; e0 < E; e0 += stride) {
        // ---- gather 16 edges into the warp's smem tile ----
#pragma unroll
        for (int p = 0; p < 4; p++) {
            long e = e0 + p * 4 + g;
            long ec = (e < E) ? e : E - 1;
            int s = is64 ? (int)__ldg((const long long*)srcraw + ec)
                         : __ldg((const int*)srcraw + ec);
            int d = is64 ? (int)__ldg((const long long*)dstraw + ec)
                         : __ldg((const int*)dstraw + ec);
            const uint4* Up = (const uint4*)g_Uh + (size_t)s * 16 + hl * 2;
            const uint4* Ip = (const uint4*)g_Ih + (size_t)d * 16 + hl * 2;
            uint4 u0 = Up[0], u1 = Up[1];
            uint4 v0 = Ip[0], v1 = Ip[1];

            uint4 ra, rb;
            {
                const __half2* ua = (const __half2*)&u0;
                const __half2* va = (const __half2*)&v0;
                __half2 h0 = __hmax2(__hadd2(ua[0], va[0]), z2);
                __half2 h1 = __hmax2(__hadd2(ua[1], va[1]), z2);
                __half2 h2 = __hmax2(__hadd2(ua[2], va[2]), z2);
                __half2 h3 = __hmax2(__hadd2(ua[3], va[3]), z2);
                ra = make_uint4(*(unsigned*)&h0, *(unsigned*)&h1,
                                *(unsigned*)&h2, *(unsigned*)&h3);
                const __half2* ub = (const __half2*)&u1;
                const __half2* vb = (const __half2*)&v1;
                __half2 h4 = __hmax2(__hadd2(ub[0], vb[0]), z2);
                __half2 h5 = __hmax2(__hadd2(ub[1], vb[1]), z2);
                __half2 h6 = __hmax2(__hadd2(ub[2], vb[2]), z2);
                __half2 h7 = __hmax2(__hadd2(ub[3], vb[3]), z2);
                rb = make_uint4(*(unsigned*)&h4, *(unsigned*)&h5,
                                *(unsigned*)&h6, *(unsigned*)&h7);
            }
            int r = p * 4 + g;                 // row in tile 0..15
            unsigned sw = (unsigned)((r & 7) << 4);
            unsigned off0 = r * 256 + ((hl * 32) ^ sw);
            unsigned off1 = r * 256 + ((hl * 32 + 16) ^ sw);
            *(uint4*)(hp + off0) = ra;
            *(uint4*)(hp + off1) = rb;
        }
        __syncwarp();

        // ---- mma over k=128 ----
        float acc0 = 0.f, acc1 = 0.f, acc2 = 0.f, acc3 = 0.f;
        int rr = (lane & 7) + ((lane >> 3) & 1) * 8;   // ldmatrix row
        int khalf = (lane >> 4) * 16;                  // 0 or 16 bytes
        unsigned rowsw = (unsigned)((rr & 7) << 4);
        unsigned abase = su32(hp) + rr * 256;
#pragma unroll
        for (int kt = 0; kt < 8; kt++) {
            unsigned addr = abase + (((unsigned)(kt * 32 + khalf)) ^ rowsw);
            unsigned a0, a1, a2, a3;
            asm volatile("ldmatrix.sync.aligned.m8n8.x4.shared.b16 "
                         "{%0,%1,%2,%3}, [%4];"
                         : "=r"(a0), "=r"(a1), "=r"(a2), "=r"(a3)
                         : "r"(addr));
            asm volatile("mma.sync.aligned.m16n8k16.row.col.f32.f16.f16.f32 "
                         "{%0,%1,%2,%3}, {%4,%5,%6,%7}, {%8,%9}, {%0,%1,%2,%3};"
                         : "+f"(acc0), "+f"(acc1), "+f"(acc2), "+f"(acc3)
                         : "r"(a0), "r"(a1), "r"(a2), "r"(a3),
                           "r"(bfrag[kt][0]), "r"(bfrag[kt][1]));
        }
        __syncwarp();   // protect smem WAR vs next chunk's gather

        // ---- store: c0/c1 -> row lane>>2, cols cA/cB; c2/c3 -> row+8 ----
        long eA = e0 + (lane >> 2);
        long eBr = eA + 8;
        if (cA < NCLS) {
            if (eA < E)  out[eA * NCLS + cA] = acc0 + bA;
            if (eBr < E) out[eBr * NCLS + cA] = acc2 + bA;
        }
        if (cB < NCLS) {
            if (eA < E)  out[eA * NCLS + cB] = acc1 + bB;
            if (eBr < E) out[eBr * NCLS + cB] = acc3 + bB;
        }
    }
}

// ---------------------------------------------------------------------------
// Inputs (metadata order): ufeat, ifeat, W1, b1, W2, b2, src_idx, dst_idx
// ---------------------------------------------------------------------------
extern "C" void kernel_launch(void* const* d_in, const int* in_sizes, int n_in,
                              void* d_out, int out_size) {
    const float* ufeat = (const float*)d_in[0];
    const float* ifeat = (const float*)d_in[1];
    const float* W1    = (const float*)d_in[2];
    const float* b1    = (const float*)d_in[3];
    const float* W2    = (const float*)d_in[4];
    const float* b2    = (const float*)d_in[5];
    const void*  src   = d_in[6];
    const void*  dst   = d_in[7];

    int nu = in_sizes[0] / DD;
    int nm = in_sizes[1] / DD;
    int E  = in_sizes[6];

    int blocksU = (nu + 127) / 128;
    int blocksI = (nm + 127) / 128;
    pre2_kernel<<<blocksU + blocksI, 256>>>(ufeat, ifeat, W1, b1, nu, nm, blocksU);

    edge_mma_kernel<<<444, 256>>>(W2, b2, src, dst, (float*)d_out, (long)E);
}

// round 9
// speedup vs baseline: 2.1187x; 1.0531x over previous
#include <cuda_runtime.h>
#include <cuda_fp16.h>
#include <cstdint>

#define DD    64
#define HID   128
#define NCLS  5
#define MAXU  100000
#define MAXM  50000

// Scratch (allocation-free per harness rules). U/I stored as fp16.
__device__ unsigned short g_Uh[(size_t)MAXU * HID];   // 25.6 MB
__device__ unsigned short g_Ih[(size_t)MAXM * HID];   // 12.8 MB

// ---- packed f32x2 helpers (sm_100) ----
__device__ __forceinline__ unsigned long long ffma2(unsigned long long a,
                                                    unsigned long long b,
                                                    unsigned long long c) {
    unsigned long long d;
    asm("fma.rn.f32x2 %0, %1, %2, %3;" : "=l"(d) : "l"(a), "l"(b), "l"(c));
    return d;
}
__device__ __forceinline__ float2 u2f(unsigned long long v) {
    float2 r;
    asm("mov.b64 {%0, %1}, %2;" : "=f"(r.x), "=f"(r.y) : "l"(v));
    return r;
}

// ---------------------------------------------------------------------------
// Pre v4: register-tiled GEMM (R4/R6 math), but the W smem tile stores each
// column value DUPLICATED as packed f32x2 pairs, grouped so each compute
// LDS.128 reads 256B of consecutive chunks (2-cyc, no conflicts). This
// removes the 8 pack MOVs per k-step that were 17% of the issue stream.
//   Fs[32][128]          16KB  features transposed [k][row]
//   Wd[k][m][t] chunks   32KB  chunk(k,m,t) = {w[c],w[c],w[c+1],w[c+1]},
//                              c = t*8 + 2m   (t=0..15, m=0..3)
// Math order identical to R6 -> bit-identical U/I.
// ---------------------------------------------------------------------------
__global__ void __launch_bounds__(256, 2)
pre4_kernel(const float* __restrict__ ufeat, const float* __restrict__ ifeat,
            const float* __restrict__ W1, const float* __restrict__ b1,
            int nu, int nm, int blocksU) {
    __shared__ __align__(16) float Fs[32 * 128];        // 16KB
    __shared__ __align__(16) float Wd[32 * 4 * 16 * 4]; // 32KB (total 48KB)

    bool isU = (int)blockIdx.x < blocksU;
    int rowbase = (isU ? blockIdx.x : blockIdx.x - blocksU) * 128;
    int nrows = isU ? nu : nm;
    const float4* F4 = (const float4*)(isU ? ufeat : ifeat);   // row = 16 float4
    const float4* W14 = (const float4*)W1;                     // row = 32 float4
    int woff = isU ? 0 : 16;
    unsigned short* outb = isU ? g_Uh : g_Ih;

    int tid = threadIdx.x;
    int tr = tid >> 4, tc = tid & 15;
    int r0 = tr * 8, c0 = tc * 8;

    unsigned long long acc[4][8];
#pragma unroll
    for (int a = 0; a < 4; a++)
#pragma unroll
        for (int j = 0; j < 8; j++) acc[a][j] = 0ULL;

#pragma unroll
    for (int h = 0; h < 2; h++) {
        if (h) __syncthreads();
#pragma unroll
        for (int it = 0; it < 4; it++) {
            int idx = it * 256 + tid;        // 0..1023
            int r = idx >> 3;                // 0..127 (F row / W col)
            int f = idx & 7;                 // float4 within k-half
            int kq = f * 4;
            int rr = rowbase + r;
            if (rr >= nrows) rr = nrows - 1;
            float4 v = F4[(size_t)rr * 16 + h * 8 + f];
            Fs[(kq + 0) * 128 + r] = v.x;
            Fs[(kq + 1) * 128 + r] = v.y;
            Fs[(kq + 2) * 128 + r] = v.z;
            Fs[(kq + 3) * 128 + r] = v.w;
            // W fill: col c=r supplies 2 dup floats of chunk (k, m, t)
            float4 u = W14[(size_t)r * 32 + woff + h * 8 + f];
            int t = r >> 3, mm = (r & 7) >> 1, ho = (r & 1) * 2;
            float uu[4] = {u.x, u.y, u.z, u.w};
#pragma unroll
            for (int q = 0; q < 4; q++) {
                float* bp = &Wd[(((kq + q) * 4 + mm) * 16 + t) * 4 + ho];
                bp[0] = uu[q];
                bp[1] = uu[q];
            }
        }
        __syncthreads();

#pragma unroll 4
        for (int k = 0; k < 32; k++) {
            const unsigned long long* frow =
                (const unsigned long long*)&Fs[k * 128 + r0];
            unsigned long long f2[4];
            f2[0] = frow[0]; f2[1] = frow[1]; f2[2] = frow[2]; f2[3] = frow[3];
            ulonglong2 wd2[4];
#pragma unroll
            for (int m = 0; m < 4; m++)
                wd2[m] = *(const ulonglong2*)&Wd[((k * 4 + m) * 16 + tc) * 4];
#pragma unroll
            for (int rp = 0; rp < 4; rp++) {
#pragma unroll
                for (int m = 0; m < 4; m++) {
                    acc[rp][2 * m]     = ffma2(f2[rp], wd2[m].x, acc[rp][2 * m]);
                    acc[rp][2 * m + 1] = ffma2(f2[rp], wd2[m].y, acc[rp][2 * m + 1]);
                }
            }
        }
    }

    float bv[8];
#pragma unroll
    for (int j = 0; j < 8; j++) bv[j] = 0.f;
    if (!isU) {
#pragma unroll
        for (int j = 0; j < 8; j++) bv[j] = b1[c0 + j];
    }

#pragma unroll
    for (int rp = 0; rp < 4; rp++) {
        float x[8], y[8];
#pragma unroll
        for (int j = 0; j < 8; j++) {
            float2 t = u2f(acc[rp][j]);
            x[j] = t.x + bv[j];
            y[j] = t.y + bv[j];
        }
        int rowA = rowbase + r0 + rp * 2;
        int rowB = rowA + 1;
        if (rowA < nrows) {
            __half2 h0 = __floats2half2_rn(x[0], x[1]);
            __half2 h1 = __floats2half2_rn(x[2], x[3]);
            __half2 h2 = __floats2half2_rn(x[4], x[5]);
            __half2 h3 = __floats2half2_rn(x[6], x[7]);
            *(uint4*)(outb + (size_t)rowA * HID + c0) =
                make_uint4(*(unsigned*)&h0, *(unsigned*)&h1,
                           *(unsigned*)&h2, *(unsigned*)&h3);
        }
        if (rowB < nrows) {
            __half2 h0 = __floats2half2_rn(y[0], y[1]);
            __half2 h1 = __floats2half2_rn(y[2], y[3]);
            __half2 h2 = __floats2half2_rn(y[4], y[5]);
            __half2 h3 = __floats2half2_rn(y[6], y[7]);
            *(uint4*)(outb + (size_t)rowB * HID + c0) =
                make_uint4(*(unsigned*)&h0, *(unsigned*)&h1,
                           *(unsigned*)&h2, *(unsigned*)&h3);
        }
    }
}

// ---------------------------------------------------------------------------
// Edge MMA kernel (R8 winner + coalesced gather). Lane hl now reads
// Up[hl] / Up[hl+8]: each 8-lane group's LDG.128 covers exactly one 128B
// cache line (was stride-32B spanning two lines) -> gather L1 wavefronts
// halve. k order in the smem row is unchanged (natural 0..127).
// ---------------------------------------------------------------------------
__device__ __forceinline__ unsigned su32(const void* p) {
    return (unsigned)__cvta_generic_to_shared(p);
}

__global__ void __launch_bounds__(256, 3)
edge_mma_kernel(const float* __restrict__ W2, const float* __restrict__ b2,
                const void* __restrict__ srcraw, const void* __restrict__ dstraw,
                float* __restrict__ out, long E) {
    __shared__ __align__(128) unsigned char hs[8 * 16 * 256];  // 32KB, 4KB/warp

    int tid = threadIdx.x;
    int w = tid >> 5, lane = tid & 31;
    unsigned char* hp = hs + w * 4096;

    // ---- inline is64 probe (identical result in every warp) ----
    long n64avail = E / 2;
    int pid = (lane < n64avail) ? lane : 0;
    unsigned long long pv = ((const unsigned long long*)srcraw)[pid];
    unsigned bigmask = __ballot_sync(0xffffffffu, pv >= 200000ULL);
    int is64 = (bigmask == 0u);

    // ---- B fragments: W2 as fp16 in mma.m16n8k16 col layout, built once ----
    int nB = lane >> 2;
    int kb = (lane & 3) * 2;
    unsigned bfrag[8][2];
#pragma unroll
    for (int kt = 0; kt < 8; kt++) {
#pragma unroll
        for (int j = 0; j < 2; j++) {
            int k0 = kt * 16 + kb + j * 8;
            float f0 = (nB < NCLS) ? __ldg(W2 + nB * HID + k0) : 0.f;
            float f1 = (nB < NCLS) ? __ldg(W2 + nB * HID + k0 + 1) : 0.f;
            __half2 hh = __floats2half2_rn(f0, f1);
            bfrag[kt][j] = *(unsigned*)&hh;
        }
    }
    int cA = (lane & 3) * 2, cB = cA + 1;
    float bA = (cA < NCLS) ? __ldg(b2 + cA) : 0.f;
    float bB = (cB < NCLS) ? __ldg(b2 + cB) : 0.f;

    int g = lane >> 3, hl = lane & 7;
    __half2 z2 = __float2half2_rn(0.f);

    long chunk0 = ((long)blockIdx.x * 8 + w) * 16;
    long stride = (long)gridDim.x * 8 * 16;

    for (long e0 = chunk0; e0 < E; e0 += stride) {
        // ---- gather 16 edges into the warp's smem tile (coalesced) ----
#pragma unroll
        for (int p = 0; p < 4; p++) {
            long e = e0 + p * 4 + g;
            long ec = (e < E) ? e : E - 1;
            int s = is64 ? (int)__ldg((const long long*)srcraw + ec)
                         : __ldg((const int*)srcraw + ec);
            int d = is64 ? (int)__ldg((const long long*)dstraw + ec)
                         : __ldg((const int*)dstraw + ec);
            const uint4* Up = (const uint4*)g_Uh + (size_t)s * 16;
            const uint4* Ip = (const uint4*)g_Ih + (size_t)d * 16;
            uint4 u0 = Up[hl], u1 = Up[hl + 8];     // line 0 / line 1
            uint4 v0 = Ip[hl], v1 = Ip[hl + 8];

            uint4 ra, rb;
            {
                const __half2* ua = (const __half2*)&u0;
                const __half2* va = (const __half2*)&v0;
                __half2 h0 = __hmax2(__hadd2(ua[0], va[0]), z2);
                __half2 h1 = __hmax2(__hadd2(ua[1], va[1]), z2);
                __half2 h2 = __hmax2(__hadd2(ua[2], va[2]), z2);
                __half2 h3 = __hmax2(__hadd2(ua[3], va[3]), z2);
                ra = make_uint4(*(unsigned*)&h0, *(unsigned*)&h1,
                                *(unsigned*)&h2, *(unsigned*)&h3);
                const __half2* ub = (const __half2*)&u1;
                const __half2* vb = (const __half2*)&v1;
                __half2 h4 = __hmax2(__hadd2(ub[0], vb[0]), z2);
                __half2 h5 = __hmax2(__hadd2(ub[1], vb[1]), z2);
                __half2 h6 = __hmax2(__hadd2(ub[2], vb[2]), z2);
                __half2 h7 = __hmax2(__hadd2(ub[3], vb[3]), z2);
                rb = make_uint4(*(unsigned*)&h4, *(unsigned*)&h5,
                                *(unsigned*)&h6, *(unsigned*)&h7);
            }
            int r = p * 4 + g;                 // row in tile 0..15
            unsigned sw = (unsigned)((r & 7) << 4);
            unsigned off0 = r * 256 + ((hl * 16) ^ sw);          // k 0..63
            unsigned off1 = r * 256 + ((128 + hl * 16) ^ sw);    // k 64..127
            *(uint4*)(hp + off0) = ra;
            *(uint4*)(hp + off1) = rb;
        }
        __syncwarp();

        // ---- mma over k=128 ----
        float acc0 = 0.f, acc1 = 0.f, acc2 = 0.f, acc3 = 0.f;
        int rr = (lane & 7) + ((lane >> 3) & 1) * 8;   // ldmatrix row
        int khalf = (lane >> 4) * 16;                  // 0 or 16 bytes
        unsigned rowsw = (unsigned)((rr & 7) << 4);
        unsigned abase = su32(hp) + rr * 256;
#pragma unroll
        for (int kt = 0; kt < 8; kt++) {
            unsigned addr = abase + (((unsigned)(kt * 32 + khalf)) ^ rowsw);
            unsigned a0, a1, a2, a3;
            asm volatile("ldmatrix.sync.aligned.m8n8.x4.shared.b16 "
                         "{%0,%1,%2,%3}, [%4];"
                         : "=r"(a0), "=r"(a1), "=r"(a2), "=r"(a3)
                         : "r"(addr));
            asm volatile("mma.sync.aligned.m16n8k16.row.col.f32.f16.f16.f32 "
                         "{%0,%1,%2,%3}, {%4,%5,%6,%7}, {%8,%9}, {%0,%1,%2,%3};"
                         : "+f"(acc0), "+f"(acc1), "+f"(acc2), "+f"(acc3)
                         : "r"(a0), "r"(a1), "r"(a2), "r"(a3),
                           "r"(bfrag[kt][0]), "r"(bfrag[kt][1]));
        }
        __syncwarp();   // protect smem WAR vs next chunk's gather

        // ---- store: c0/c1 -> row lane>>2, cols cA/cB; c2/c3 -> row+8 ----
        long eA = e0 + (lane >> 2);
        long eBr = eA + 8;
        if (cA < NCLS) {
            if (eA < E)  out[eA * NCLS + cA] = acc0 + bA;
            if (eBr < E) out[eBr * NCLS + cA] = acc2 + bA;
        }
        if (cB < NCLS) {
            if (eA < E)  out[eA * NCLS + cB] = acc1 + bB;
            if (eBr < E) out[eBr * NCLS + cB] = acc3 + bB;
        }
    }
}

// ---------------------------------------------------------------------------
// Inputs (metadata order): ufeat, ifeat, W1, b1, W2, b2, src_idx, dst_idx
// ---------------------------------------------------------------------------
extern "C" void kernel_launch(void* const* d_in, const int* in_sizes, int n_in,
                              void* d_out, int out_size) {
    const float* ufeat = (const float*)d_in[0];
    const float* ifeat = (const float*)d_in[1];
    const float* W1    = (const float*)d_in[2];
    const float* b1    = (const float*)d_in[3];
    const float* W2    = (const float*)d_in[4];
    const float* b2    = (const float*)d_in[5];
    const void*  src   = d_in[6];
    const void*  dst   = d_in[7];

    int nu = in_sizes[0] / DD;
    int nm = in_sizes[1] / DD;
    int E  = in_sizes[6];

    int blocksU = (nu + 127) / 128;
    int blocksI = (nm + 127) / 128;
    pre4_kernel<<<blocksU + blocksI, 256>>>(ufeat, ifeat, W1, b1, nu, nm, blocksU);

    edge_mma_kernel<<<444, 256>>>(W2, b2, src, dst, (float*)d_out, (long)E);
}

// round 10
// speedup vs baseline: 2.3347x; 1.1019x over previous
#include <cuda_runtime.h>
#include <cuda_fp16.h>
#include <cstdint>

#define DD    64
#define HID   128
#define NCLS  5
#define MAXU  100000
#define MAXM  50000

// Scratch (allocation-free per harness rules). U/I stored as fp16.
__device__ unsigned short g_Uh[(size_t)MAXU * HID];   // 25.6 MB
__device__ unsigned short g_Ih[(size_t)MAXM * HID];   // 12.8 MB

// ---- packed f32x2 helpers (sm_100) ----
__device__ __forceinline__ unsigned long long ffma2(unsigned long long a,
                                                    unsigned long long b,
                                                    unsigned long long c) {
    unsigned long long d;
    asm("fma.rn.f32x2 %0, %1, %2, %3;" : "=l"(d) : "l"(a), "l"(b), "l"(c));
    return d;
}
__device__ __forceinline__ float2 u2f(unsigned long long v) {
    float2 r;
    asm("mov.b64 {%0, %1}, %2;" : "=f"(r.x), "=f"(r.y) : "l"(v));
    return r;
}
__device__ __forceinline__ unsigned long long pack2(float x, float y) {
    unsigned long long r;
    asm("mov.b64 %0, {%1, %2};" : "=l"(r) : "f"(x), "f"(y));
    return r;
}

// ---------------------------------------------------------------------------
// Pre v2 (R4/R6/R8-proven, ~55us): register-tiled GEMM. Block = 256 threads
// (16tr x 16tc), thread tile 8 rows x 8 cols, k=64 in 2 halves of 32
// (two 16KB transposed smem tiles). FFMA2 packed over ROW PAIRS.
// (pre4's duplicated-W variant reverted: its fill was 16-way bank-conflicted
//  -> +20us. This version's pack MOVs are cheaper than those conflicts.)
// ---------------------------------------------------------------------------
__global__ void __launch_bounds__(256, 2)
pre2_kernel(const float* __restrict__ ufeat, const float* __restrict__ ifeat,
            const float* __restrict__ W1, const float* __restrict__ b1,
            int nu, int nm, int blocksU) {
    __shared__ __align__(16) float Fs[32 * 128];   // 16KB [k][row]
    __shared__ __align__(16) float Wt[32 * 128];   // 16KB [k][col]

    bool isU = (int)blockIdx.x < blocksU;
    int rowbase = (isU ? blockIdx.x : blockIdx.x - blocksU) * 128;
    int nrows = isU ? nu : nm;
    const float4* F4 = (const float4*)(isU ? ufeat : ifeat);   // row = 16 float4
    const float4* W14 = (const float4*)W1;                     // row = 32 float4
    int woff = isU ? 0 : 16;
    unsigned short* outb = isU ? g_Uh : g_Ih;

    int tid = threadIdx.x;
    int tr = tid >> 4, tc = tid & 15;
    int r0 = tr * 8, c0 = tc * 8;

    unsigned long long acc[4][8];
#pragma unroll
    for (int a = 0; a < 4; a++)
#pragma unroll
        for (int j = 0; j < 8; j++) acc[a][j] = 0ULL;

#pragma unroll
    for (int h = 0; h < 2; h++) {
        if (h) __syncthreads();
#pragma unroll
        for (int it = 0; it < 4; it++) {
            int idx = it * 256 + tid;        // 0..1023
            int r = idx >> 3;                // 0..127 (row or col)
            int f = idx & 7;                 // float4 within k-half
            int rr = rowbase + r;
            if (rr >= nrows) rr = nrows - 1;
            float4 v = F4[(size_t)rr * 16 + h * 8 + f];
            Fs[(f * 4 + 0) * 128 + r] = v.x;
            Fs[(f * 4 + 1) * 128 + r] = v.y;
            Fs[(f * 4 + 2) * 128 + r] = v.z;
            Fs[(f * 4 + 3) * 128 + r] = v.w;
            float4 u = W14[(size_t)r * 32 + woff + h * 8 + f];
            Wt[(f * 4 + 0) * 128 + r] = u.x;
            Wt[(f * 4 + 1) * 128 + r] = u.y;
            Wt[(f * 4 + 2) * 128 + r] = u.z;
            Wt[(f * 4 + 3) * 128 + r] = u.w;
        }
        __syncthreads();

#pragma unroll 4
        for (int k = 0; k < 32; k++) {
            const unsigned long long* frow =
                (const unsigned long long*)&Fs[k * 128 + r0];
            unsigned long long f2[4];
            f2[0] = frow[0]; f2[1] = frow[1]; f2[2] = frow[2]; f2[3] = frow[3];
            float4 wa = *(const float4*)&Wt[k * 128 + c0];
            float4 wb = *(const float4*)&Wt[k * 128 + c0 + 4];
            unsigned long long wd[8];
            wd[0] = pack2(wa.x, wa.x); wd[1] = pack2(wa.y, wa.y);
            wd[2] = pack2(wa.z, wa.z); wd[3] = pack2(wa.w, wa.w);
            wd[4] = pack2(wb.x, wb.x); wd[5] = pack2(wb.y, wb.y);
            wd[6] = pack2(wb.z, wb.z); wd[7] = pack2(wb.w, wb.w);
#pragma unroll
            for (int rp = 0; rp < 4; rp++)
#pragma unroll
                for (int j = 0; j < 8; j++)
                    acc[rp][j] = ffma2(f2[rp], wd[j], acc[rp][j]);
        }
    }

    float bv[8];
#pragma unroll
    for (int j = 0; j < 8; j++) bv[j] = 0.f;
    if (!isU) {
#pragma unroll
        for (int j = 0; j < 8; j++) bv[j] = b1[c0 + j];
    }

#pragma unroll
    for (int rp = 0; rp < 4; rp++) {
        float x[8], y[8];
#pragma unroll
        for (int j = 0; j < 8; j++) {
            float2 t = u2f(acc[rp][j]);
            x[j] = t.x + bv[j];
            y[j] = t.y + bv[j];
        }
        int rowA = rowbase + r0 + rp * 2;
        int rowB = rowA + 1;
        if (rowA < nrows) {
            __half2 h0 = __floats2half2_rn(x[0], x[1]);
            __half2 h1 = __floats2half2_rn(x[2], x[3]);
            __half2 h2 = __floats2half2_rn(x[4], x[5]);
            __half2 h3 = __floats2half2_rn(x[6], x[7]);
            *(uint4*)(outb + (size_t)rowA * HID + c0) =
                make_uint4(*(unsigned*)&h0, *(unsigned*)&h1,
                           *(unsigned*)&h2, *(unsigned*)&h3);
        }
        if (rowB < nrows) {
            __half2 h0 = __floats2half2_rn(y[0], y[1]);
            __half2 h1 = __floats2half2_rn(y[2], y[3]);
            __half2 h2 = __floats2half2_rn(y[4], y[5]);
            __half2 h3 = __floats2half2_rn(y[6], y[7]);
            *(uint4*)(outb + (size_t)rowB * HID + c0) =
                make_uint4(*(unsigned*)&h0, *(unsigned*)&h1,
                           *(unsigned*)&h2, *(unsigned*)&h3);
        }
    }
}

// ---------------------------------------------------------------------------
// Edge MMA kernel (R9-proven, 54.9us). 16-edge chunks per warp, coalesced
// line-granular gather, fp16 relu-add, ldmatrix + mma.m16n8k16 vs register-
// resident W2 fragments, fp32 accumulate, predicated stores.
// ---------------------------------------------------------------------------
__device__ __forceinline__ unsigned su32(const void* p) {
    return (unsigned)__cvta_generic_to_shared(p);
}

__global__ void __launch_bounds__(256, 3)
edge_mma_kernel(const float* __restrict__ W2, const float* __restrict__ b2,
                const void* __restrict__ srcraw, const void* __restrict__ dstraw,
                float* __restrict__ out, long E) {
    __shared__ __align__(128) unsigned char hs[8 * 16 * 256];  // 32KB, 4KB/warp

    int tid = threadIdx.x;
    int w = tid >> 5, lane = tid & 31;
    unsigned char* hp = hs + w * 4096;

    // ---- inline is64 probe (identical result in every warp) ----
    long n64avail = E / 2;
    int pid = (lane < n64avail) ? lane : 0;
    unsigned long long pv = ((const unsigned long long*)srcraw)[pid];
    unsigned bigmask = __ballot_sync(0xffffffffu, pv >= 200000ULL);
    int is64 = (bigmask == 0u);

    // ---- B fragments: W2 as fp16 in mma.m16n8k16 col layout, built once ----
    int nB = lane >> 2;
    int kb = (lane & 3) * 2;
    unsigned bfrag[8][2];
#pragma unroll
    for (int kt = 0; kt < 8; kt++) {
#pragma unroll
        for (int j = 0; j < 2; j++) {
            int k0 = kt * 16 + kb + j * 8;
            float f0 = (nB < NCLS) ? __ldg(W2 + nB * HID + k0) : 0.f;
            float f1 = (nB < NCLS) ? __ldg(W2 + nB * HID + k0 + 1) : 0.f;
            __half2 hh = __floats2half2_rn(f0, f1);
            bfrag[kt][j] = *(unsigned*)&hh;
        }
    }
    int cA = (lane & 3) * 2, cB = cA + 1;
    float bA = (cA < NCLS) ? __ldg(b2 + cA) : 0.f;
    float bB = (cB < NCLS) ? __ldg(b2 + cB) : 0.f;

    int g = lane >> 3, hl = lane & 7;
    __half2 z2 = __float2half2_rn(0.f);

    long chunk0 = ((long)blockIdx.x * 8 + w) * 16;
    long stride = (long)gridDim.x * 8 * 16;

    for (long e0 = chunk0; e0 < E; e0 += stride) {
        // ---- gather 16 edges into the warp's smem tile (coalesced) ----
#pragma unroll
        for (int p = 0; p < 4; p++) {
            long e = e0 + p * 4 + g;
            long ec = (e < E) ? e : E - 1;
            int s = is64 ? (int)__ldg((const long long*)srcraw + ec)
                         : __ldg((const int*)srcraw + ec);
            int d = is64 ? (int)__ldg((const long long*)dstraw + ec)
                         : __ldg((const int*)dstraw + ec);
            const uint4* Up = (const uint4*)g_Uh + (size_t)s * 16;
            const uint4* Ip = (const uint4*)g_Ih + (size_t)d * 16;
            uint4 u0 = Up[hl], u1 = Up[hl + 8];     // line 0 / line 1
            uint4 v0 = Ip[hl], v1 = Ip[hl + 8];

            uint4 ra, rb;
            {
                const __half2* ua = (const __half2*)&u0;
                const __half2* va = (const __half2*)&v0;
                __half2 h0 = __hmax2(__hadd2(ua[0], va[0]), z2);
                __half2 h1 = __hmax2(__hadd2(ua[1], va[1]), z2);
                __half2 h2 = __hmax2(__hadd2(ua[2], va[2]), z2);
                __half2 h3 = __hmax2(__hadd2(ua[3], va[3]), z2);
                ra = make_uint4(*(unsigned*)&h0, *(unsigned*)&h1,
                                *(unsigned*)&h2, *(unsigned*)&h3);
                const __half2* ub = (const __half2*)&u1;
                const __half2* vb = (const __half2*)&v1;
                __half2 h4 = __hmax2(__hadd2(ub[0], vb[0]), z2);
                __half2 h5 = __hmax2(__hadd2(ub[1], vb[1]), z2);
                __half2 h6 = __hmax2(__hadd2(ub[2], vb[2]), z2);
                __half2 h7 = __hmax2(__hadd2(ub[3], vb[3]), z2);
                rb = make_uint4(*(unsigned*)&h4, *(unsigned*)&h5,
                                *(unsigned*)&h6, *(unsigned*)&h7);
            }
            int r = p * 4 + g;                 // row in tile 0..15
            unsigned sw = (unsigned)((r & 7) << 4);
            unsigned off0 = r * 256 + ((hl * 16) ^ sw);          // k 0..63
            unsigned off1 = r * 256 + ((128 + hl * 16) ^ sw);    // k 64..127
            *(uint4*)(hp + off0) = ra;
            *(uint4*)(hp + off1) = rb;
        }
        __syncwarp();

        // ---- mma over k=128 ----
        float acc0 = 0.f, acc1 = 0.f, acc2 = 0.f, acc3 = 0.f;
        int rr = (lane & 7) + ((lane >> 3) & 1) * 8;   // ldmatrix row
        int khalf = (lane >> 4) * 16;                  // 0 or 16 bytes
        unsigned rowsw = (unsigned)((rr & 7) << 4);
        unsigned abase = su32(hp) + rr * 256;
#pragma unroll
        for (int kt = 0; kt < 8; kt++) {
            unsigned addr = abase + (((unsigned)(kt * 32 + khalf)) ^ rowsw);
            unsigned a0, a1, a2, a3;
            asm volatile("ldmatrix.sync.aligned.m8n8.x4.shared.b16 "
                         "{%0,%1,%2,%3}, [%4];"
                         : "=r"(a0), "=r"(a1), "=r"(a2), "=r"(a3)
                         : "r"(addr));
            asm volatile("mma.sync.aligned.m16n8k16.row.col.f32.f16.f16.f32 "
                         "{%0,%1,%2,%3}, {%4,%5,%6,%7}, {%8,%9}, {%0,%1,%2,%3};"
                         : "+f"(acc0), "+f"(acc1), "+f"(acc2), "+f"(acc3)
                         : "r"(a0), "r"(a1), "r"(a2), "r"(a3),
                           "r"(bfrag[kt][0]), "r"(bfrag[kt][1]));
        }
        __syncwarp();   // protect smem WAR vs next chunk's gather

        // ---- store: c0/c1 -> row lane>>2, cols cA/cB; c2/c3 -> row+8 ----
        long eA = e0 + (lane >> 2);
        long eBr = eA + 8;
        if (cA < NCLS) {
            if (eA < E)  out[eA * NCLS + cA] = acc0 + bA;
            if (eBr < E) out[eBr * NCLS + cA] = acc2 + bA;
        }
        if (cB < NCLS) {
            if (eA < E)  out[eA * NCLS + cB] = acc1 + bB;
            if (eBr < E) out[eBr * NCLS + cB] = acc3 + bB;
        }
    }
}

// ---------------------------------------------------------------------------
// Inputs (metadata order): ufeat, ifeat, W1, b1, W2, b2, src_idx, dst_idx
// ---------------------------------------------------------------------------
extern "C" void kernel_launch(void* const* d_in, const int* in_sizes, int n_in,
                              void* d_out, int out_size) {
    const float* ufeat = (const float*)d_in[0];
    const float* ifeat = (const float*)d_in[1];
    const float* W1    = (const float*)d_in[2];
    const float* b1    = (const float*)d_in[3];
    const float* W2    = (const float*)d_in[4];
    const float* b2    = (const float*)d_in[5];
    const void*  src   = d_in[6];
    const void*  dst   = d_in[7];

    int nu = in_sizes[0] / DD;
    int nm = in_sizes[1] / DD;
    int E  = in_sizes[6];

    int blocksU = (nu + 127) / 128;
    int blocksI = (nm + 127) / 128;
    pre2_kernel<<<blocksU + blocksI, 256>>>(ufeat, ifeat, W1, b1, nu, nm, blocksU);

    edge_mma_kernel<<<444, 256>>>(W2, b2, src, dst, (float*)d_out, (long)E);
}

// round 12
// speedup vs baseline: 2.4152x; 1.0345x over previous
#include <cuda_runtime.h>
#include <cuda_fp16.h>
#include <cstdint>

#define DD    64
#define HID   128
#define NCLS  5
#define MAXU  100000
#define MAXM  50000

// Scratch (allocation-free per harness rules). U/I stored as fp16.
__device__ unsigned short g_Uh[(size_t)MAXU * HID];   // 25.6 MB
__device__ unsigned short g_Ih[(size_t)MAXM * HID];   // 12.8 MB

// ---- packed f32x2 helpers (sm_100) ----
__device__ __forceinline__ unsigned long long ffma2(unsigned long long a,
                                                    unsigned long long b,
                                                    unsigned long long c) {
    unsigned long long d;
    asm("fma.rn.f32x2 %0, %1, %2, %3;" : "=l"(d) : "l"(a), "l"(b), "l"(c));
    return d;
}
__device__ __forceinline__ float2 u2f(unsigned long long v) {
    float2 r;
    asm("mov.b64 {%0, %1}, %2;" : "=f"(r.x), "=f"(r.y) : "l"(v));
    return r;
}
__device__ __forceinline__ unsigned long long pack2(float x, float y) {
    unsigned long long r;
    asm("mov.b64 %0, {%1, %2};" : "=l"(r) : "f"(x), "f"(y));
    return r;
}

// 16B-chunk XOR swizzle keyed on (k>>2): fi is a float index 0..127 within a
// k-row. Fill stores have k = 4f+q so (k>>2)=f carries full lane entropy ->
// conflict-free transpose stores; compute reads are a per-k bijection of
// 16B chunks -> still broadcast/conflict-free, alignment preserved.
#define SWF(k, fi) ((((((fi) >> 2) ^ (((k) >> 2) & 7))) << 2) | ((fi) & 3))

// ---------------------------------------------------------------------------
// Pre v5 = pre2 (proven math, FFMA2 row-pair tiles) + conflict-free swizzled
// tile fills. Block = 256 threads (16tr x 16tc), thread tile 8 rows x 8 cols,
// k=64 in 2 halves of 32 (two 16KB transposed smem tiles).
// FFMA2 order identical to pre2 -> bit-identical U/I.
// ---------------------------------------------------------------------------
__global__ void __launch_bounds__(256, 2)
pre5_kernel(const float* __restrict__ ufeat, const float* __restrict__ ifeat,
            const float* __restrict__ W1, const float* __restrict__ b1,
            int nu, int nm, int blocksU) {
    __shared__ __align__(16) float Fs[32 * 128];   // 16KB [k][row swz]
    __shared__ __align__(16) float Wt[32 * 128];   // 16KB [k][col swz]

    bool isU = (int)blockIdx.x < blocksU;
    int rowbase = (isU ? blockIdx.x : blockIdx.x - blocksU) * 128;
    int nrows = isU ? nu : nm;
    const float4* F4 = (const float4*)(isU ? ufeat : ifeat);   // row = 16 float4
    const float4* W14 = (const float4*)W1;                     // row = 32 float4
    int woff = isU ? 0 : 16;
    unsigned short* outb = isU ? g_Uh : g_Ih;

    int tid = threadIdx.x;
    int tr = tid >> 4, tc = tid & 15;
    int r0 = tr * 8, c0 = tc * 8;

    unsigned long long acc[4][8];
#pragma unroll
    for (int a = 0; a < 4; a++)
#pragma unroll
        for (int j = 0; j < 8; j++) acc[a][j] = 0ULL;

#pragma unroll
    for (int h = 0; h < 2; h++) {
        if (h) __syncthreads();
#pragma unroll
        for (int it = 0; it < 4; it++) {
            int idx = it * 256 + tid;        // 0..1023
            int r = idx >> 3;                // 0..127 (row or col)
            int f = idx & 7;                 // float4 within k-half
            int kq = f * 4;
            int rr = rowbase + r;
            if (rr >= nrows) rr = nrows - 1;
            float4 v = F4[(size_t)rr * 16 + h * 8 + f];
            Fs[(kq + 0) * 128 + SWF(kq + 0, r)] = v.x;
            Fs[(kq + 1) * 128 + SWF(kq + 1, r)] = v.y;
            Fs[(kq + 2) * 128 + SWF(kq + 2, r)] = v.z;
            Fs[(kq + 3) * 128 + SWF(kq + 3, r)] = v.w;
            float4 u = W14[(size_t)r * 32 + woff + h * 8 + f];
            Wt[(kq + 0) * 128 + SWF(kq + 0, r)] = u.x;
            Wt[(kq + 1) * 128 + SWF(kq + 1, r)] = u.y;
            Wt[(kq + 2) * 128 + SWF(kq + 2, r)] = u.z;
            Wt[(kq + 3) * 128 + SWF(kq + 3, r)] = u.w;
        }
        __syncthreads();

#pragma unroll 4
        for (int k = 0; k < 32; k++) {
            unsigned long long f2[4];
#pragma unroll
            for (int rp = 0; rp < 4; rp++)
                f2[rp] = *(const unsigned long long*)
                             &Fs[k * 128 + SWF(k, r0 + 2 * rp)];
            float4 wa = *(const float4*)&Wt[k * 128 + SWF(k, c0)];
            float4 wb = *(const float4*)&Wt[k * 128 + SWF(k, c0 + 4)];
            unsigned long long wd[8];
            wd[0] = pack2(wa.x, wa.x); wd[1] = pack2(wa.y, wa.y);
            wd[2] = pack2(wa.z, wa.z); wd[3] = pack2(wa.w, wa.w);
            wd[4] = pack2(wb.x, wb.x); wd[5] = pack2(wb.y, wb.y);
            wd[6] = pack2(wb.z, wb.z); wd[7] = pack2(wb.w, wb.w);
#pragma unroll
            for (int rp = 0; rp < 4; rp++)
#pragma unroll
                for (int j = 0; j < 8; j++)
                    acc[rp][j] = ffma2(f2[rp], wd[j], acc[rp][j]);
        }
    }

    float bv[8];
#pragma unroll
    for (int j = 0; j < 8; j++) bv[j] = 0.f;
    if (!isU) {
#pragma unroll
        for (int j = 0; j < 8; j++) bv[j] = b1[c0 + j];
    }

#pragma unroll
    for (int rp = 0; rp < 4; rp++) {
        float x[8], y[8];
#pragma unroll
        for (int j = 0; j < 8; j++) {
            float2 t = u2f(acc[rp][j]);
            x[j] = t.x + bv[j];
            y[j] = t.y + bv[j];
        }
        int rowA = rowbase + r0 + rp * 2;
        int rowB = rowA + 1;
        if (rowA < nrows) {
            __half2 h0 = __floats2half2_rn(x[0], x[1]);
            __half2 h1 = __floats2half2_rn(x[2], x[3]);
            __half2 h2 = __floats2half2_rn(x[4], x[5]);
            __half2 h3 = __floats2half2_rn(x[6], x[7]);
            *(uint4*)(outb + (size_t)rowA * HID + c0) =
                make_uint4(*(unsigned*)&h0, *(unsigned*)&h1,
                           *(unsigned*)&h2, *(unsigned*)&h3);
        }
        if (rowB < nrows) {
            __half2 h0 = __floats2half2_rn(y[0], y[1]);
            __half2 h1 = __floats2half2_rn(y[2], y[3]);
            __half2 h2 = __floats2half2_rn(y[4], y[5]);
            __half2 h3 = __floats2half2_rn(y[6], y[7]);
            *(uint4*)(outb + (size_t)rowB * HID + c0) =
                make_uint4(*(unsigned*)&h0, *(unsigned*)&h1,
                           *(unsigned*)&h2, *(unsigned*)&h3);
        }
    }
}

// ---------------------------------------------------------------------------
// Edge MMA kernel (R9/R10-proven, 55.0us — unchanged). 16-edge chunks per
// warp, coalesced line-granular gather, fp16 relu-add, ldmatrix +
// mma.m16n8k16 vs register-resident W2 fragments, fp32 accumulate.
// ---------------------------------------------------------------------------
__device__ __forceinline__ unsigned su32(const void* p) {
    return (unsigned)__cvta_generic_to_shared(p);
}

__global__ void __launch_bounds__(256, 3)
edge_mma_kernel(const float* __restrict__ W2, const float* __restrict__ b2,
                const void* __restrict__ srcraw, const void* __restrict__ dstraw,
                float* __restrict__ out, long E) {
    __shared__ __align__(128) unsigned char hs[8 * 16 * 256];  // 32KB, 4KB/warp

    int tid = threadIdx.x;
    int w = tid >> 5, lane = tid & 31;
    unsigned char* hp = hs + w * 4096;

    // ---- inline is64 probe (identical result in every warp) ----
    long n64avail = E / 2;
    int pid = (lane < n64avail) ? lane : 0;
    unsigned long long pv = ((const unsigned long long*)srcraw)[pid];
    unsigned bigmask = __ballot_sync(0xffffffffu, pv >= 200000ULL);
    int is64 = (bigmask == 0u);

    // ---- B fragments: W2 as fp16 in mma.m16n8k16 col layout, built once ----
    int nB = lane >> 2;
    int kb = (lane & 3) * 2;
    unsigned bfrag[8][2];
#pragma unroll
    for (int kt = 0; kt < 8; kt++) {
#pragma unroll
        for (int j = 0; j < 2; j++) {
            int k0 = kt * 16 + kb + j * 8;
            float f0 = (nB < NCLS) ? __ldg(W2 + nB * HID + k0) : 0.f;
            float f1 = (nB < NCLS) ? __ldg(W2 + nB * HID + k0 + 1) : 0.f;
            __half2 hh = __floats2half2_rn(f0, f1);
            bfrag[kt][j] = *(unsigned*)&hh;
        }
    }
    int cA = (lane & 3) * 2, cB = cA + 1;
    float bA = (cA < NCLS) ? __ldg(b2 + cA) : 0.f;
    float bB = (cB < NCLS) ? __ldg(b2 + cB) : 0.f;

    int g = lane >> 3, hl = lane & 7;
    __half2 z2 = __float2half2_rn(0.f);

    long chunk0 = ((long)blockIdx.x * 8 + w) * 16;
    long stride = (long)gridDim.x * 8 * 16;

    for (long e0 = chunk0; e0 < E; e0 += stride) {
        // ---- gather 16 edges into the warp's smem tile (coalesced) ----
#pragma unroll
        for (int p = 0; p < 4; p++) {
            long e = e0 + p * 4 + g;
            long ec = (e < E) ? e : E - 1;
            int s = is64 ? (int)__ldg((const long long*)srcraw + ec)
                         : __ldg((const int*)srcraw + ec);
            int d = is64 ? (int)__ldg((const long long*)dstraw + ec)
                         : __ldg((const int*)dstraw + ec);
            const uint4* Up = (const uint4*)g_Uh + (size_t)s * 16;
            const uint4* Ip = (const uint4*)g_Ih + (size_t)d * 16;
            uint4 u0 = Up[hl], u1 = Up[hl + 8];     // line 0 / line 1
            uint4 v0 = Ip[hl], v1 = Ip[hl + 8];

            uint4 ra, rb;
            {
                const __half2* ua = (const __half2*)&u0;
                const __half2* va = (const __half2*)&v0;
                __half2 h0 = __hmax2(__hadd2(ua[0], va[0]), z2);
                __half2 h1 = __hmax2(__hadd2(ua[1], va[1]), z2);
                __half2 h2 = __hmax2(__hadd2(ua[2], va[2]), z2);
                __half2 h3 = __hmax2(__hadd2(ua[3], va[3]), z2);
                ra = make_uint4(*(unsigned*)&h0, *(unsigned*)&h1,
                                *(unsigned*)&h2, *(unsigned*)&h3);
                const __half2* ub = (const __half2*)&u1;
                const __half2* vb = (const __half2*)&v1;
                __half2 h4 = __hmax2(__hadd2(ub[0], vb[0]), z2);
                __half2 h5 = __hmax2(__hadd2(ub[1], vb[1]), z2);
                __half2 h6 = __hmax2(__hadd2(ub[2], vb[2]), z2);
                __half2 h7 = __hmax2(__hadd2(ub[3], vb[3]), z2);
                rb = make_uint4(*(unsigned*)&h4, *(unsigned*)&h5,
                                *(unsigned*)&h6, *(unsigned*)&h7);
            }
            int r = p * 4 + g;                 // row in tile 0..15
            unsigned sw = (unsigned)((r & 7) << 4);
            unsigned off0 = r * 256 + ((hl * 16) ^ sw);          // k 0..63
            unsigned off1 = r * 256 + ((128 + hl * 16) ^ sw);    // k 64..127
            *(uint4*)(hp + off0) = ra;
            *(uint4*)(hp + off1) = rb;
        }
        __syncwarp();

        // ---- mma over k=128 ----
        float acc0 = 0.f, acc1 = 0.f, acc2 = 0.f, acc3 = 0.f;
        int rr = (lane & 7) + ((lane >> 3) & 1) * 8;   // ldmatrix row
        int khalf = (lane >> 4) * 16;                  // 0 or 16 bytes
        unsigned rowsw = (unsigned)((rr & 7) << 4);
        unsigned abase = su32(hp) + rr * 256;
#pragma unroll
        for (int kt = 0; kt < 8; kt++) {
            unsigned addr = abase + (((unsigned)(kt * 32 + khalf)) ^ rowsw);
            unsigned a0, a1, a2, a3;
            asm volatile("ldmatrix.sync.aligned.m8n8.x4.shared.b16 "
                         "{%0,%1,%2,%3}, [%4];"
                         : "=r"(a0), "=r"(a1), "=r"(a2), "=r"(a3)
                         : "r"(addr));
            asm volatile("mma.sync.aligned.m16n8k16.row.col.f32.f16.f16.f32 "
                         "{%0,%1,%2,%3}, {%4,%5,%6,%7}, {%8,%9}, {%0,%1,%2,%3};"
                         : "+f"(acc0), "+f"(acc1), "+f"(acc2), "+f"(acc3)
                         : "r"(a0), "r"(a1), "r"(a2), "r"(a3),
                           "r"(bfrag[kt][0]), "r"(bfrag[kt][1]));
        }
        __syncwarp();   // protect smem WAR vs next chunk's gather

        // ---- store: c0/c1 -> row lane>>2, cols cA/cB; c2/c3 -> row+8 ----
        long eA = e0 + (lane >> 2);
        long eBr = eA + 8;
        if (cA < NCLS) {
            if (eA < E)  out[eA * NCLS + cA] = acc0 + bA;
            if (eBr < E) out[eBr * NCLS + cA] = acc2 + bA;
        }
        if (cB < NCLS) {
            if (eA < E)  out[eA * NCLS + cB] = acc1 + bB;
            if (eBr < E) out[eBr * NCLS + cB] = acc3 + bB;
        }
    }
}

// ---------------------------------------------------------------------------
// Inputs (metadata order): ufeat, ifeat, W1, b1, W2, b2, src_idx, dst_idx
// ---------------------------------------------------------------------------
extern "C" void kernel_launch(void* const* d_in, const int* in_sizes, int n_in,
                              void* d_out, int out_size) {
    const float* ufeat = (const float*)d_in[0];
    const float* ifeat = (const float*)d_in[1];
    const float* W1    = (const float*)d_in[2];
    const float* b1    = (const float*)d_in[3];
    const float* W2    = (const float*)d_in[4];
    const float* b2    = (const float*)d_in[5];
    const void*  src   = d_in[6];
    const void*  dst   = d_in[7];

    int nu = in_sizes[0] / DD;
    int nm = in_sizes[1] / DD;
    int E  = in_sizes[6];

    int blocksU = (nu + 127) / 128;
    int blocksI = (nm + 127) / 128;
    pre5_kernel<<<blocksU + blocksI, 256>>>(ufeat, ifeat, W1, b1, nu, nm, blocksU);

    edge_mma_kernel<<<444, 256>>>(W2, b2, src, dst, (float*)d_out, (long)E);
}